// round 7
// baseline (speedup 1.0000x reference)
#include <cuda_runtime.h>
#include <cuda_bf16.h>
#include <cstdint>

#define N_TASKS   8
#define D_MODEL   1024
#define HIDDEN    1024
#define N_CLASSES 100
#define BATCH     8192
#define KDIM      1024

#define BM 128
#define BN 128
#define BK 32
#define NSTAGE 3
#define ASTR 40                       // A smem row stride (bf16), 80B — ldmatrix conflict-free
#define BSTR 136                      // B smem row stride (bf16), 272B — ldmatrix.trans conflict-free
#define A_ELEMS (BM * ASTR)           // 5120
#define B_ELEMS (BK * BSTR)           // 4352
#define STAGE_ELEMS (2 * A_ELEMS + 2 * B_ELEMS)   // 18944
#define STAGE_B (STAGE_ELEMS * 2)                 // 37888 bytes
#define DYN_SMEM (NSTAGE * STAGE_B)               // 113664 bytes -> 2 CTAs/SM

// ---------------- device scratch (no allocations allowed) ----------------
__device__ int            g_counts[N_TASKS];
__device__ int            g_rowids[N_TASKS * BATCH];
__device__ __nv_bfloat16  g_xh[BATCH * D_MODEL];
__device__ __nv_bfloat16  g_xl[BATCH * D_MODEL];
__device__ __nv_bfloat16  g_w1h[N_TASKS * D_MODEL * HIDDEN];   // [t][k][n] natural
__device__ __nv_bfloat16  g_w1l[N_TASKS * D_MODEL * HIDDEN];
__device__ __nv_bfloat16  g_w2h[N_TASKS * KDIM * 128];         // [t][k][n pad 128]
__device__ __nv_bfloat16  g_w2l[N_TASKS * KDIM * 128];
__device__ __nv_bfloat16  g_hh[BATCH * HIDDEN];
__device__ __nv_bfloat16  g_hl[BATCH * HIDDEN];
__device__ float          g_part[2 * BATCH * 128];             // split-K=2 partials

// ---------------- PTX helpers ----------------
__device__ __forceinline__ uint32_t s2u(const void* p) {
    return (uint32_t)__cvta_generic_to_shared(p);
}
__device__ __forceinline__ void cp16(uint32_t dst, const void* src, bool v) {
    int sz = v ? 16 : 0;
    asm volatile("cp.async.cg.shared.global [%0], [%1], 16, %2;\n"
                 :: "r"(dst), "l"(src), "r"(sz));
}
#define CP_COMMIT asm volatile("cp.async.commit_group;\n" ::: "memory")
#define CP_WAIT1  asm volatile("cp.async.wait_group 1;\n" ::: "memory")
#define CP_WAIT0  asm volatile("cp.async.wait_group 0;\n" ::: "memory")

__device__ __forceinline__ void ldsm4(uint32_t* r, uint32_t addr) {
    asm volatile("ldmatrix.sync.aligned.m8n8.x4.shared.b16 {%0,%1,%2,%3}, [%4];"
                 : "=r"(r[0]), "=r"(r[1]), "=r"(r[2]), "=r"(r[3]) : "r"(addr));
}
__device__ __forceinline__ void ldsm4t(uint32_t* r, uint32_t addr) {
    asm volatile("ldmatrix.sync.aligned.m8n8.x4.trans.shared.b16 {%0,%1,%2,%3}, [%4];"
                 : "=r"(r[0]), "=r"(r[1]), "=r"(r[2]), "=r"(r[3]) : "r"(addr));
}
__device__ __forceinline__ void mma_bf16(float* c, const uint32_t* a, const uint32_t* b) {
    asm volatile(
        "mma.sync.aligned.m16n8k16.row.col.f32.bf16.bf16.f32 "
        "{%0,%1,%2,%3}, {%4,%5,%6,%7}, {%8,%9}, {%0,%1,%2,%3};\n"
        : "+f"(c[0]), "+f"(c[1]), "+f"(c[2]), "+f"(c[3])
        : "r"(a[0]), "r"(a[1]), "r"(a[2]), "r"(a[3]), "r"(b[0]), "r"(b[1]));
}

// ---------------- bucketing ----------------
__global__ void zero_counts_kernel() {
    if (threadIdx.x < N_TASKS) g_counts[threadIdx.x] = 0;
}
__global__ void bucket_rows_kernel(const int* __restrict__ task_id) {
    int b = blockIdx.x * blockDim.x + threadIdx.x;
    if (b < BATCH) {
        int t = task_id[b];
        int pos = atomicAdd(&g_counts[t], 1);
        g_rowids[t * BATCH + pos] = b;
    }
}

// ---------------- fp32 -> bf16 hi/lo splits ----------------
__global__ void split_kernel(const float* __restrict__ src,
                             __nv_bfloat16* __restrict__ dh,
                             __nv_bfloat16* __restrict__ dl, int n8) {
    int i = blockIdx.x * blockDim.x + threadIdx.x;
    if (i >= n8) return;
    float4 v0 = ((const float4*)src)[2 * i];
    float4 v1 = ((const float4*)src)[2 * i + 1];
    float v[8] = {v0.x, v0.y, v0.z, v0.w, v1.x, v1.y, v1.z, v1.w};
    alignas(16) __nv_bfloat16 h[8];
    alignas(16) __nv_bfloat16 l[8];
    #pragma unroll
    for (int k = 0; k < 8; k++) {
        __nv_bfloat16 hb = __float2bfloat16(v[k]);
        h[k] = hb;
        l[k] = __float2bfloat16(v[k] - __bfloat162float(hb));
    }
    ((uint4*)dh)[i] = *(uint4*)h;
    ((uint4*)dl)[i] = *(uint4*)l;
}

// W2 [T*K][100] -> padded [T*K][128] hi/lo bf16 (zero pad)
__global__ void split_w2_kernel(const float* __restrict__ W2,
                                __nv_bfloat16* __restrict__ dh,
                                __nv_bfloat16* __restrict__ dl) {
    int i = blockIdx.x * blockDim.x + threadIdx.x;      // (T*K) * 32
    if (i >= N_TASKS * KDIM * 32) return;
    int row = i >> 5, q = i & 31, c = q * 4;
    float v[4] = {0.f, 0.f, 0.f, 0.f};
    if (c < N_CLASSES) {
        float4 tv = *(const float4*)(W2 + (size_t)row * N_CLASSES + c);
        v[0] = tv.x; v[1] = tv.y; v[2] = tv.z; v[3] = tv.w;
    }
    alignas(8) __nv_bfloat16 h[4];
    alignas(8) __nv_bfloat16 l[4];
    #pragma unroll
    for (int k = 0; k < 4; k++) {
        __nv_bfloat16 hb = __float2bfloat16(v[k]);
        h[k] = hb;
        l[k] = __float2bfloat16(v[k] - __bfloat162float(hb));
    }
    ((uint2*)(dh + (size_t)row * 128))[q] = *(uint2*)h;
    ((uint2*)(dl + (size_t)row * 128))[q] = *(uint2*)l;
}

// ---------------- grouped GEMM, 3-term bf16 split, HMMA ----------------
// MODE 0: layer1 — blockIdx.x = n-tile; bias+relu; bf16 hi/lo out (ld=HIDDEN)
// MODE 1: layer2 — blockIdx.x = k-chunk (of 2); fp32 partials to g_part
template<int MODE>
__global__ __launch_bounds__(256, 2)
void gemm_kernel(const __nv_bfloat16* __restrict__ Ah,
                 const __nv_bfloat16* __restrict__ Al,
                 const __nv_bfloat16* __restrict__ Bh_,
                 const __nv_bfloat16* __restrict__ Bl_,
                 const float* __restrict__ bias,
                 __nv_bfloat16* __restrict__ Dh,
                 __nv_bfloat16* __restrict__ Dl,
                 int K, int ldB, int strideB_task) {
    const int t   = blockIdx.z;
    const int cnt = g_counts[t];
    const int m0  = blockIdx.y * BM;
    if (m0 >= cnt) return;

    int n0, kb0, KB;
    if (MODE == 0) { n0 = blockIdx.x * BN; kb0 = 0;                      KB = K / BK; }
    else           { n0 = 0;               kb0 = blockIdx.x * (K / (2 * BK)); KB = K / (2 * BK); }

    const __nv_bfloat16* Bh = Bh_ + (size_t)t * strideB_task;
    const __nv_bfloat16* Bl = Bl_ + (size_t)t * strideB_task;

    extern __shared__ __nv_bfloat16 sm[];
    __shared__ int rowid_s[BM];

    const int tid = threadIdx.x;
    if (tid < BM) {
        int m = m0 + tid;
        rowid_s[tid] = (m < cnt) ? g_rowids[t * BATCH + m] : -1;
    }
    __syncthreads();

    // ---- loader state ----
    // A: 512 16B-chunks per array (128 rows x 4 chunks of 8 bf16); units tid, tid+256
    const int arow0 = tid >> 2,         ac0 = tid & 3;
    const int arow1 = (tid + 256) >> 2, ac1 = (tid + 256) & 3;
    const int rA0 = rowid_s[arow0], rA1 = rowid_s[arow1];
    const bool av0 = (rA0 >= 0), av1 = (rA1 >= 0);
    const char* aH0 = (const char*)(Ah + (size_t)(av0 ? rA0 : 0) * K) + (size_t)(kb0 * 64) + ac0 * 16;
    const char* aH1 = (const char*)(Ah + (size_t)(av1 ? rA1 : 0) * K) + (size_t)(kb0 * 64) + ac1 * 16;
    const char* aL0 = (const char*)(Al + (size_t)(av0 ? rA0 : 0) * K) + (size_t)(kb0 * 64) + ac0 * 16;
    const char* aL1 = (const char*)(Al + (size_t)(av1 ? rA1 : 0) * K) + (size_t)(kb0 * 64) + ac1 * 16;
    const uint32_t aoff0 = (uint32_t)(arow0 * ASTR + ac0 * 8) * 2;
    const uint32_t aoff1 = (uint32_t)(arow1 * ASTR + ac1 * 8) * 2;

    // B: 512 16B-chunks per array (32 k-rows x 16 chunks of 8 bf16); units tid, tid+256
    const int bk0 = tid >> 4,         bc0 = tid & 15;
    const int bk1 = (tid + 256) >> 4, bc1 = (tid + 256) & 15;
    const char* bH0 = (const char*)(Bh + (size_t)(kb0 * BK + bk0) * ldB + n0 + bc0 * 8);
    const char* bH1 = (const char*)(Bh + (size_t)(kb0 * BK + bk1) * ldB + n0 + bc1 * 8);
    const char* bL0 = (const char*)(Bl + (size_t)(kb0 * BK + bk0) * ldB + n0 + bc0 * 8);
    const char* bL1 = (const char*)(Bl + (size_t)(kb0 * BK + bk1) * ldB + n0 + bc1 * 8);
    const uint32_t boff0 = (uint32_t)(bk0 * BSTR + bc0 * 8) * 2;
    const uint32_t boff1 = (uint32_t)(bk1 * BSTR + bc1 * 8) * 2;
    const size_t bstep = (size_t)BK * ldB * 2;   // bytes per k-block

    const uint32_t smu = s2u(sm);

    auto issue = [&](int stage, int kb) {
        uint32_t base = smu + stage * STAGE_B;
        size_t akb = (size_t)kb * 64;            // 32 bf16 = 64B per row per k-block
        size_t bkb = (size_t)kb * bstep;
        cp16(base + aoff0, aH0 + akb, av0);
        cp16(base + aoff1, aH1 + akb, av1);
        cp16(base + 2 * A_ELEMS + aoff0, aL0 + akb, av0);
        cp16(base + 2 * A_ELEMS + aoff1, aL1 + akb, av1);
        cp16(base + 4 * A_ELEMS + boff0, bH0 + bkb, true);
        cp16(base + 4 * A_ELEMS + boff1, bH1 + bkb, true);
        cp16(base + 4 * A_ELEMS + 2 * B_ELEMS + boff0, bL0 + bkb, true);
        cp16(base + 4 * A_ELEMS + 2 * B_ELEMS + boff1, bL1 + bkb, true);
    };

    // ---- compute lane mapping ----
    const int warp = tid >> 5, lane = tid & 31;
    const int wm = warp >> 2;           // 0..1 (m half)
    const int wn = warp & 3;            // 0..3 (n quarter)
    const int g  = lane >> 2, tg = lane & 3;
    // A ldmatrix.x4: lanes 0-7 rows, 8-15 rows+8, 16-31 k+8
    const uint32_t a_lane = (uint32_t)(((wm * 64 + (lane & 7) + ((lane >> 3) & 1) * 8) * ASTR
                                        + ((lane >> 4) & 1) * 8) * 2);
    // B ldmatrix.x4.trans: lanes 0-7 k-rows, 8-15 k+8, 16-31 n+8
    const uint32_t b_lane = (uint32_t)((((lane & 7) + ((lane >> 3) & 1) * 8) * BSTR
                                        + ((lane >> 4) & 1) * 8 + wn * 32) * 2);

    float acc[4][4][4];
    #pragma unroll
    for (int i = 0; i < 4; i++)
        #pragma unroll
        for (int j = 0; j < 4; j++)
            #pragma unroll
            for (int q = 0; q < 4; q++) acc[i][j][q] = 0.f;

    auto compute = [&](int stage) {
        uint32_t base = smu + stage * STAGE_B;
        uint32_t uAh = base;
        uint32_t uAl = base + 2 * A_ELEMS;
        uint32_t uBh = base + 4 * A_ELEMS;
        uint32_t uBl = base + 4 * A_ELEMS + 2 * B_ELEMS;
        #pragma unroll
        for (int kk = 0; kk < BK; kk += 16) {
            uint32_t bh[2][4], bl[2][4];          // [jj][4 regs] -> j tiles 2jj, 2jj+1
            #pragma unroll
            for (int jj = 0; jj < 2; jj++) {
                uint32_t off = b_lane + (uint32_t)((kk * BSTR + jj * 16) * 2);
                ldsm4t(bh[jj], uBh + off);
                ldsm4t(bl[jj], uBl + off);
            }
            #pragma unroll
            for (int i = 0; i < 4; i++) {
                uint32_t ah[4], al[4];
                uint32_t off = a_lane + (uint32_t)((i * 16 * ASTR + kk) * 2);
                ldsm4(ah, uAh + off);
                ldsm4(al, uAl + off);
                #pragma unroll
                for (int j = 0; j < 4; j++) {
                    const uint32_t* bhf = &bh[j >> 1][(j & 1) * 2];
                    const uint32_t* blf = &bl[j >> 1][(j & 1) * 2];
                    mma_bf16(acc[i][j], ah, bhf);
                    mma_bf16(acc[i][j], ah, blf);
                    mma_bf16(acc[i][j], al, bhf);
                }
            }
        }
    };

    // ---- 3-stage pipelined mainloop, one sync per iteration ----
    issue(0, 0); CP_COMMIT;
    issue(1, 1); CP_COMMIT;
    for (int kb = 0; kb < KB; kb++) {
        if (kb + 1 < KB) { CP_WAIT1; } else { CP_WAIT0; }
        __syncthreads();
        if (kb + 2 < KB) { issue((kb + 2) % NSTAGE, kb + 2); CP_COMMIT; }
        compute(kb % NSTAGE);
    }

    // ---- epilogue ----
    if (MODE == 0) {
        const float* bT = bias + (size_t)t * HIDDEN;
        #pragma unroll
        for (int j = 0; j < 4; j++) {
            int c = n0 + wn * 32 + j * 8 + 2 * tg;
            float bc0 = bT[c], bc1 = bT[c + 1];
            #pragma unroll
            for (int i = 0; i < 4; i++) {
                int lr = wm * 64 + i * 16 + g;
                int r0 = rowid_s[lr], r1 = rowid_s[lr + 8];
                if (r0 >= 0) {
                    float v0 = acc[i][j][0] + bc0; v0 = v0 > 0.f ? v0 : 0.f;
                    float v1 = acc[i][j][1] + bc1; v1 = v1 > 0.f ? v1 : 0.f;
                    __nv_bfloat16 h0 = __float2bfloat16(v0), h1 = __float2bfloat16(v1);
                    __nv_bfloat16 l0 = __float2bfloat16(v0 - __bfloat162float(h0));
                    __nv_bfloat16 l1 = __float2bfloat16(v1 - __bfloat162float(h1));
                    *(__nv_bfloat162*)&Dh[(size_t)r0 * HIDDEN + c] = __nv_bfloat162(h0, h1);
                    *(__nv_bfloat162*)&Dl[(size_t)r0 * HIDDEN + c] = __nv_bfloat162(l0, l1);
                }
                if (r1 >= 0) {
                    float v0 = acc[i][j][2] + bc0; v0 = v0 > 0.f ? v0 : 0.f;
                    float v1 = acc[i][j][3] + bc1; v1 = v1 > 0.f ? v1 : 0.f;
                    __nv_bfloat16 h0 = __float2bfloat16(v0), h1 = __float2bfloat16(v1);
                    __nv_bfloat16 l0 = __float2bfloat16(v0 - __bfloat162float(h0));
                    __nv_bfloat16 l1 = __float2bfloat16(v1 - __bfloat162float(h1));
                    *(__nv_bfloat162*)&Dh[(size_t)r1 * HIDDEN + c] = __nv_bfloat162(h0, h1);
                    *(__nv_bfloat162*)&Dl[(size_t)r1 * HIDDEN + c] = __nv_bfloat162(l0, l1);
                }
            }
        }
    } else {
        float* P = g_part + (size_t)blockIdx.x * BATCH * 128;
        #pragma unroll
        for (int j = 0; j < 4; j++) {
            int c = wn * 32 + j * 8 + 2 * tg;
            #pragma unroll
            for (int i = 0; i < 4; i++) {
                int lr = wm * 64 + i * 16 + g;
                int r0 = rowid_s[lr], r1 = rowid_s[lr + 8];
                if (r0 >= 0)
                    *(float2*)(P + (size_t)r0 * 128 + c) = make_float2(acc[i][j][0], acc[i][j][1]);
                if (r1 >= 0)
                    *(float2*)(P + (size_t)r1 * 128 + c) = make_float2(acc[i][j][2], acc[i][j][3]);
            }
        }
    }
}

// ---------------- split-K reduce + bias for layer2 ----------------
__global__ void reduce_kernel(const int* __restrict__ task_id,
                              const float* __restrict__ b2,
                              float* __restrict__ out) {
    int i = blockIdx.x * blockDim.x + threadIdx.x;   // BATCH * 25
    if (i >= BATCH * 25) return;
    int r = i / 25, q = i % 25, c = q * 4;
    int t = task_id[r];
    float4 s0 = *(const float4*)(g_part + ((size_t)0 * BATCH + r) * 128 + c);
    float4 s1 = *(const float4*)(g_part + ((size_t)1 * BATCH + r) * 128 + c);
    float4 b  = *(const float4*)(b2 + (size_t)t * N_CLASSES + c);
    float4 o;
    o.x = s0.x + s1.x + b.x;
    o.y = s0.y + s1.y + b.y;
    o.z = s0.z + s1.z + b.z;
    o.w = s0.w + s1.w + b.w;
    *(float4*)(out + (size_t)r * N_CLASSES + c) = o;
}

// ---------------- launcher ----------------
extern "C" void kernel_launch(void* const* d_in, const int* in_sizes, int n_in,
                              void* d_out, int out_size) {
    (void)in_sizes; (void)n_in; (void)out_size;
    const float* x       = (const float*)d_in[0];
    const int*   task_id = (const int*)  d_in[1];
    const float* W1      = (const float*)d_in[2];
    const float* b1      = (const float*)d_in[3];
    const float* W2      = (const float*)d_in[4];
    const float* b2      = (const float*)d_in[5];
    float*       out     = (float*)d_out;

    static __nv_bfloat16 *p_xh = nullptr, *p_xl, *p_w1h, *p_w1l, *p_w2h, *p_w2l, *p_hh, *p_hl;
    static bool attr_done = false;
    if (!p_xh) {
        cudaGetSymbolAddress((void**)&p_xh,  g_xh);
        cudaGetSymbolAddress((void**)&p_xl,  g_xl);
        cudaGetSymbolAddress((void**)&p_w1h, g_w1h);
        cudaGetSymbolAddress((void**)&p_w1l, g_w1l);
        cudaGetSymbolAddress((void**)&p_w2h, g_w2h);
        cudaGetSymbolAddress((void**)&p_w2l, g_w2l);
        cudaGetSymbolAddress((void**)&p_hh,  g_hh);
        cudaGetSymbolAddress((void**)&p_hl,  g_hl);
    }
    if (!attr_done) {
        cudaFuncSetAttribute(gemm_kernel<0>, cudaFuncAttributeMaxDynamicSharedMemorySize, DYN_SMEM);
        cudaFuncSetAttribute(gemm_kernel<1>, cudaFuncAttributeMaxDynamicSharedMemorySize, DYN_SMEM);
        attr_done = true;
    }

    zero_counts_kernel<<<1, 32>>>();
    bucket_rows_kernel<<<(BATCH + 255) / 256, 256>>>(task_id);

    const int n8x = BATCH * D_MODEL / 8;
    split_kernel<<<(n8x + 255) / 256, 256>>>(x, p_xh, p_xl, n8x);
    const int n8w = N_TASKS * D_MODEL * HIDDEN / 8;
    split_kernel<<<(n8w + 255) / 256, 256>>>(W1, p_w1h, p_w1l, n8w);
    split_w2_kernel<<<(N_TASKS * KDIM * 32 + 255) / 256, 256>>>(W2, p_w2h, p_w2l);

    // layer 1: h = relu(x @ W1[t] + b1[t]) -> bf16 hi/lo
    dim3 g1(HIDDEN / BN, BATCH / BM, N_TASKS);
    gemm_kernel<0><<<g1, 256, DYN_SMEM>>>(p_xh, p_xl, p_w1h, p_w1l, b1,
                                          p_hh, p_hl, D_MODEL, HIDDEN, D_MODEL * HIDDEN);

    // layer 2: split-K=2 partials
    dim3 g2(2, BATCH / BM, N_TASKS);
    gemm_kernel<1><<<g2, 256, DYN_SMEM>>>(p_hh, p_hl, p_w2h, p_w2l, nullptr,
                                          nullptr, nullptr, KDIM, 128, KDIM * 128);

    // reduce + bias -> out
    reduce_kernel<<<(BATCH * 25 + 255) / 256, 256>>>(task_id, b2, out);
}

// round 8
// speedup vs baseline: 1.0777x; 1.0777x over previous
#include <cuda_runtime.h>
#include <cuda_bf16.h>
#include <cstdint>

#define N_TASKS   8
#define D_MODEL   1024
#define HIDDEN    1024
#define N_CLASSES 100
#define BATCH     8192
#define KDIM      1024

#define BM 128
#define BN 128
#define BK 32
#define ASTR 40                       // A smem row stride (bf16), 80B — ldmatrix conflict-free
#define BSTR 136                      // B smem row stride (bf16), 272B — ldmatrix.trans conflict-free
#define A_ELEMS (BM * ASTR)           // 5120
#define B_ELEMS (BK * BSTR)           // 4352
#define STAGE_ELEMS (2 * A_ELEMS + 2 * B_ELEMS)   // 18944
#define STAGE_B (STAGE_ELEMS * 2)                 // 37888 bytes
#define DYN_SMEM (2 * STAGE_B)                    // 75776 bytes -> 2 CTAs/SM guaranteed

// ---------------- device scratch (no allocations allowed) ----------------
__device__ int            g_counts[N_TASKS];
__device__ int            g_rowids[N_TASKS * BATCH];
__device__ __nv_bfloat16  g_xh[BATCH * D_MODEL];
__device__ __nv_bfloat16  g_xl[BATCH * D_MODEL];
__device__ __nv_bfloat16  g_w1h[N_TASKS * D_MODEL * HIDDEN];   // [t][k][n] natural
__device__ __nv_bfloat16  g_w1l[N_TASKS * D_MODEL * HIDDEN];
__device__ __nv_bfloat16  g_w2h[N_TASKS * KDIM * 128];         // [t][k][n pad 128]
__device__ __nv_bfloat16  g_w2l[N_TASKS * KDIM * 128];
__device__ __nv_bfloat16  g_hh[BATCH * HIDDEN];
__device__ __nv_bfloat16  g_hl[BATCH * HIDDEN];
__device__ float          g_part[4 * BATCH * 128];             // split-K=4 partials

// ---------------- PTX helpers ----------------
__device__ __forceinline__ uint32_t s2u(const void* p) {
    return (uint32_t)__cvta_generic_to_shared(p);
}
__device__ __forceinline__ void cp16(uint32_t dst, const void* src, bool v) {
    int sz = v ? 16 : 0;
    asm volatile("cp.async.cg.shared.global [%0], [%1], 16, %2;\n"
                 :: "r"(dst), "l"(src), "r"(sz));
}
#define CP_COMMIT asm volatile("cp.async.commit_group;\n" ::: "memory")
#define CP_WAIT1  asm volatile("cp.async.wait_group 1;\n" ::: "memory")
#define CP_WAIT0  asm volatile("cp.async.wait_group 0;\n" ::: "memory")

__device__ __forceinline__ void ldsm4(uint32_t* r, uint32_t addr) {
    asm volatile("ldmatrix.sync.aligned.m8n8.x4.shared.b16 {%0,%1,%2,%3}, [%4];"
                 : "=r"(r[0]), "=r"(r[1]), "=r"(r[2]), "=r"(r[3]) : "r"(addr));
}
__device__ __forceinline__ void ldsm4t(uint32_t* r, uint32_t addr) {
    asm volatile("ldmatrix.sync.aligned.m8n8.x4.trans.shared.b16 {%0,%1,%2,%3}, [%4];"
                 : "=r"(r[0]), "=r"(r[1]), "=r"(r[2]), "=r"(r[3]) : "r"(addr));
}
__device__ __forceinline__ void mma_bf16(float* c, const uint32_t* a, const uint32_t* b) {
    asm volatile(
        "mma.sync.aligned.m16n8k16.row.col.f32.bf16.bf16.f32 "
        "{%0,%1,%2,%3}, {%4,%5,%6,%7}, {%8,%9}, {%0,%1,%2,%3};\n"
        : "+f"(c[0]), "+f"(c[1]), "+f"(c[2]), "+f"(c[3])
        : "r"(a[0]), "r"(a[1]), "r"(a[2]), "r"(a[3]), "r"(b[0]), "r"(b[1]));
}

// ---------------- bucketing ----------------
__global__ void zero_counts_kernel() {
    if (threadIdx.x < N_TASKS) g_counts[threadIdx.x] = 0;
}
__global__ void bucket_rows_kernel(const int* __restrict__ task_id) {
    int b = blockIdx.x * blockDim.x + threadIdx.x;
    if (b < BATCH) {
        int t = task_id[b];
        int pos = atomicAdd(&g_counts[t], 1);
        g_rowids[t * BATCH + pos] = b;
    }
}

// ---------------- fp32 -> bf16 hi/lo splits ----------------
__global__ void split_kernel(const float* __restrict__ src,
                             __nv_bfloat16* __restrict__ dh,
                             __nv_bfloat16* __restrict__ dl, int n8) {
    int i = blockIdx.x * blockDim.x + threadIdx.x;
    if (i >= n8) return;
    float4 v0 = ((const float4*)src)[2 * i];
    float4 v1 = ((const float4*)src)[2 * i + 1];
    float v[8] = {v0.x, v0.y, v0.z, v0.w, v1.x, v1.y, v1.z, v1.w};
    alignas(16) __nv_bfloat16 h[8];
    alignas(16) __nv_bfloat16 l[8];
    #pragma unroll
    for (int k = 0; k < 8; k++) {
        __nv_bfloat16 hb = __float2bfloat16(v[k]);
        h[k] = hb;
        l[k] = __float2bfloat16(v[k] - __bfloat162float(hb));
    }
    ((uint4*)dh)[i] = *(uint4*)h;
    ((uint4*)dl)[i] = *(uint4*)l;
}

// W2 [T*K][100] -> padded [T*K][128] hi/lo bf16 (zero pad)
__global__ void split_w2_kernel(const float* __restrict__ W2,
                                __nv_bfloat16* __restrict__ dh,
                                __nv_bfloat16* __restrict__ dl) {
    int i = blockIdx.x * blockDim.x + threadIdx.x;      // (T*K) * 32
    if (i >= N_TASKS * KDIM * 32) return;
    int row = i >> 5, q = i & 31, c = q * 4;
    float v[4] = {0.f, 0.f, 0.f, 0.f};
    if (c < N_CLASSES) {
        float4 tv = *(const float4*)(W2 + (size_t)row * N_CLASSES + c);
        v[0] = tv.x; v[1] = tv.y; v[2] = tv.z; v[3] = tv.w;
    }
    alignas(8) __nv_bfloat16 h[4];
    alignas(8) __nv_bfloat16 l[4];
    #pragma unroll
    for (int k = 0; k < 4; k++) {
        __nv_bfloat16 hb = __float2bfloat16(v[k]);
        h[k] = hb;
        l[k] = __float2bfloat16(v[k] - __bfloat162float(hb));
    }
    ((uint2*)(dh + (size_t)row * 128))[q] = *(uint2*)h;
    ((uint2*)(dl + (size_t)row * 128))[q] = *(uint2*)l;
}

// ---------------- grouped GEMM, 3-term bf16 split, HMMA ----------------
// MODE 0: layer1 — blockIdx.x = n-tile; bias+relu; bf16 hi/lo out (ld=HIDDEN)
// MODE 1: layer2 — blockIdx.x = k-chunk (of 4); fp32 partials to g_part
template<int MODE>
__global__ __launch_bounds__(256, 2)
void gemm_kernel(const __nv_bfloat16* __restrict__ Ah,
                 const __nv_bfloat16* __restrict__ Al,
                 const __nv_bfloat16* __restrict__ Bh_,
                 const __nv_bfloat16* __restrict__ Bl_,
                 const float* __restrict__ bias,
                 __nv_bfloat16* __restrict__ Dh,
                 __nv_bfloat16* __restrict__ Dl,
                 int K, int ldB, int strideB_task) {
    const int t   = blockIdx.z;
    const int cnt = g_counts[t];
    const int m0  = blockIdx.y * BM;
    if (m0 >= cnt) return;

    int n0, kb0, KB;
    if (MODE == 0) { n0 = blockIdx.x * BN; kb0 = 0;                          KB = K / BK; }
    else           { n0 = 0;               kb0 = blockIdx.x * (K / (4 * BK)); KB = K / (4 * BK); }

    const __nv_bfloat16* Bh = Bh_ + (size_t)t * strideB_task;
    const __nv_bfloat16* Bl = Bl_ + (size_t)t * strideB_task;

    extern __shared__ __nv_bfloat16 sm[];
    __shared__ int rowid_s[BM];

    const int tid = threadIdx.x;
    if (tid < BM) {
        int m = m0 + tid;
        rowid_s[tid] = (m < cnt) ? g_rowids[t * BATCH + m] : -1;
    }
    __syncthreads();

    // ---- loader state ----
    // A: 512 16B-chunks per array (128 rows x 4 chunks of 8 bf16); units tid, tid+256
    const int arow0 = tid >> 2,         ac0 = tid & 3;
    const int arow1 = (tid + 256) >> 2, ac1 = (tid + 256) & 3;
    const int rA0 = rowid_s[arow0], rA1 = rowid_s[arow1];
    const bool av0 = (rA0 >= 0), av1 = (rA1 >= 0);
    const char* aH0 = (const char*)(Ah + (size_t)(av0 ? rA0 : 0) * K + kb0 * BK) + ac0 * 16;
    const char* aH1 = (const char*)(Ah + (size_t)(av1 ? rA1 : 0) * K + kb0 * BK) + ac1 * 16;
    const char* aL0 = (const char*)(Al + (size_t)(av0 ? rA0 : 0) * K + kb0 * BK) + ac0 * 16;
    const char* aL1 = (const char*)(Al + (size_t)(av1 ? rA1 : 0) * K + kb0 * BK) + ac1 * 16;
    const uint32_t aoff0 = (uint32_t)(arow0 * ASTR + ac0 * 8) * 2;
    const uint32_t aoff1 = (uint32_t)(arow1 * ASTR + ac1 * 8) * 2;

    // B: 512 16B-chunks per array (32 k-rows x 16 chunks of 8 bf16); units tid, tid+256
    const int bk0 = tid >> 4,         bc0 = tid & 15;
    const int bk1 = (tid + 256) >> 4, bc1 = (tid + 256) & 15;
    const char* bH0 = (const char*)(Bh + (size_t)(kb0 * BK + bk0) * ldB + n0 + bc0 * 8);
    const char* bH1 = (const char*)(Bh + (size_t)(kb0 * BK + bk1) * ldB + n0 + bc1 * 8);
    const char* bL0 = (const char*)(Bl + (size_t)(kb0 * BK + bk0) * ldB + n0 + bc0 * 8);
    const char* bL1 = (const char*)(Bl + (size_t)(kb0 * BK + bk1) * ldB + n0 + bc1 * 8);
    const uint32_t boff0 = (uint32_t)(bk0 * BSTR + bc0 * 8) * 2;
    const uint32_t boff1 = (uint32_t)(bk1 * BSTR + bc1 * 8) * 2;
    const size_t bstep = (size_t)BK * ldB * 2;   // bytes per k-block

    const uint32_t smu = s2u(sm);

    auto issue = [&](int stage, int kb) {
        uint32_t base = smu + stage * STAGE_B;
        size_t akb = (size_t)kb * (BK * 2);      // 64 B per row per k-block
        size_t bkb = (size_t)kb * bstep;
        cp16(base + aoff0, aH0 + akb, av0);
        cp16(base + aoff1, aH1 + akb, av1);
        cp16(base + 2 * A_ELEMS + aoff0, aL0 + akb, av0);
        cp16(base + 2 * A_ELEMS + aoff1, aL1 + akb, av1);
        cp16(base + 4 * A_ELEMS + boff0, bH0 + bkb, true);
        cp16(base + 4 * A_ELEMS + boff1, bH1 + bkb, true);
        cp16(base + 4 * A_ELEMS + 2 * B_ELEMS + boff0, bL0 + bkb, true);
        cp16(base + 4 * A_ELEMS + 2 * B_ELEMS + boff1, bL1 + bkb, true);
    };

    // ---- compute lane mapping ----
    const int warp = tid >> 5, lane = tid & 31;
    const int wm = warp >> 2;           // 0..1 (m half)
    const int wn = warp & 3;            // 0..3 (n quarter)
    const int g  = lane >> 2, tg = lane & 3;
    // A ldmatrix.x4: lanes 0-7 rows, 8-15 rows+8, 16-31 k+8
    const uint32_t a_lane = (uint32_t)(((wm * 64 + (lane & 7) + ((lane >> 3) & 1) * 8) * ASTR
                                        + ((lane >> 4) & 1) * 8) * 2);
    // B ldmatrix.x4.trans: lanes 0-7 k-rows, 8-15 k+8, 16-31 n+8
    const uint32_t b_lane = (uint32_t)((((lane & 7) + ((lane >> 3) & 1) * 8) * BSTR
                                        + ((lane >> 4) & 1) * 8 + wn * 32) * 2);

    float acc[4][4][4];
    #pragma unroll
    for (int i = 0; i < 4; i++)
        #pragma unroll
        for (int j = 0; j < 4; j++)
            #pragma unroll
            for (int q = 0; q < 4; q++) acc[i][j][q] = 0.f;

    auto compute = [&](int stage) {
        uint32_t base = smu + stage * STAGE_B;
        uint32_t uAh = base;
        uint32_t uAl = base + 2 * A_ELEMS;
        uint32_t uBh = base + 4 * A_ELEMS;
        uint32_t uBl = base + 4 * A_ELEMS + 2 * B_ELEMS;
        #pragma unroll
        for (int kk = 0; kk < BK; kk += 16) {
            uint32_t bh[2][4], bl[2][4];          // [jj] -> n-tiles 2jj, 2jj+1
            #pragma unroll
            for (int jj = 0; jj < 2; jj++) {
                uint32_t off = b_lane + (uint32_t)((kk * BSTR + jj * 16) * 2);
                ldsm4t(bh[jj], uBh + off);
                ldsm4t(bl[jj], uBl + off);
            }
            #pragma unroll
            for (int i = 0; i < 4; i++) {
                uint32_t ah[4], al[4];
                uint32_t off = a_lane + (uint32_t)((i * 16 * ASTR + kk) * 2);
                ldsm4(ah, uAh + off);
                ldsm4(al, uAl + off);
                // term-major: consecutive MMAs hit different accumulators
                #pragma unroll
                for (int j = 0; j < 4; j++)
                    mma_bf16(acc[i][j], ah, &bh[j >> 1][(j & 1) * 2]);
                #pragma unroll
                for (int j = 0; j < 4; j++)
                    mma_bf16(acc[i][j], ah, &bl[j >> 1][(j & 1) * 2]);
                #pragma unroll
                for (int j = 0; j < 4; j++)
                    mma_bf16(acc[i][j], al, &bh[j >> 1][(j & 1) * 2]);
            }
        }
    };

    // ---- 2-stage pipelined mainloop (proven round-3 shape) ----
    issue(0, 0); CP_COMMIT;
    for (int kb = 0; kb < KB; kb++) {
        if (kb + 1 < KB) { issue((kb + 1) & 1, kb + 1); CP_COMMIT; CP_WAIT1; }
        else             { CP_WAIT0; }
        __syncthreads();
        compute(kb & 1);
        __syncthreads();
    }

    // ---- epilogue ----
    if (MODE == 0) {
        const float* bT = bias + (size_t)t * HIDDEN;
        #pragma unroll
        for (int j = 0; j < 4; j++) {
            int c = n0 + wn * 32 + j * 8 + 2 * tg;
            float bc0 = bT[c], bc1 = bT[c + 1];
            #pragma unroll
            for (int i = 0; i < 4; i++) {
                int lr = wm * 64 + i * 16 + g;
                int r0 = rowid_s[lr], r1 = rowid_s[lr + 8];
                if (r0 >= 0) {
                    float v0 = acc[i][j][0] + bc0; v0 = v0 > 0.f ? v0 : 0.f;
                    float v1 = acc[i][j][1] + bc1; v1 = v1 > 0.f ? v1 : 0.f;
                    __nv_bfloat16 h0 = __float2bfloat16(v0), h1 = __float2bfloat16(v1);
                    __nv_bfloat16 l0 = __float2bfloat16(v0 - __bfloat162float(h0));
                    __nv_bfloat16 l1 = __float2bfloat16(v1 - __bfloat162float(h1));
                    *(__nv_bfloat162*)&Dh[(size_t)r0 * HIDDEN + c] = __nv_bfloat162(h0, h1);
                    *(__nv_bfloat162*)&Dl[(size_t)r0 * HIDDEN + c] = __nv_bfloat162(l0, l1);
                }
                if (r1 >= 0) {
                    float v0 = acc[i][j][2] + bc0; v0 = v0 > 0.f ? v0 : 0.f;
                    float v1 = acc[i][j][3] + bc1; v1 = v1 > 0.f ? v1 : 0.f;
                    __nv_bfloat16 h0 = __float2bfloat16(v0), h1 = __float2bfloat16(v1);
                    __nv_bfloat16 l0 = __float2bfloat16(v0 - __bfloat162float(h0));
                    __nv_bfloat16 l1 = __float2bfloat16(v1 - __bfloat162float(h1));
                    *(__nv_bfloat162*)&Dh[(size_t)r1 * HIDDEN + c] = __nv_bfloat162(h0, h1);
                    *(__nv_bfloat162*)&Dl[(size_t)r1 * HIDDEN + c] = __nv_bfloat162(l0, l1);
                }
            }
        }
    } else {
        float* P = g_part + (size_t)blockIdx.x * BATCH * 128;
        #pragma unroll
        for (int j = 0; j < 4; j++) {
            int c = wn * 32 + j * 8 + 2 * tg;
            #pragma unroll
            for (int i = 0; i < 4; i++) {
                int lr = wm * 64 + i * 16 + g;
                int r0 = rowid_s[lr], r1 = rowid_s[lr + 8];
                if (r0 >= 0)
                    *(float2*)(P + (size_t)r0 * 128 + c) = make_float2(acc[i][j][0], acc[i][j][1]);
                if (r1 >= 0)
                    *(float2*)(P + (size_t)r1 * 128 + c) = make_float2(acc[i][j][2], acc[i][j][3]);
            }
        }
    }
}

// ---------------- split-K reduce + bias for layer2 ----------------
__global__ void reduce_kernel(const int* __restrict__ task_id,
                              const float* __restrict__ b2,
                              float* __restrict__ out) {
    int i = blockIdx.x * blockDim.x + threadIdx.x;   // BATCH * 25
    if (i >= BATCH * 25) return;
    int r = i / 25, q = i % 25, c = q * 4;
    int t = task_id[r];
    float4 s0 = *(const float4*)(g_part + ((size_t)0 * BATCH + r) * 128 + c);
    float4 s1 = *(const float4*)(g_part + ((size_t)1 * BATCH + r) * 128 + c);
    float4 s2 = *(const float4*)(g_part + ((size_t)2 * BATCH + r) * 128 + c);
    float4 s3 = *(const float4*)(g_part + ((size_t)3 * BATCH + r) * 128 + c);
    float4 b  = *(const float4*)(b2 + (size_t)t * N_CLASSES + c);
    float4 o;
    o.x = s0.x + s1.x + s2.x + s3.x + b.x;
    o.y = s0.y + s1.y + s2.y + s3.y + b.y;
    o.z = s0.z + s1.z + s2.z + s3.z + b.z;
    o.w = s0.w + s1.w + s2.w + s3.w + b.w;
    *(float4*)(out + (size_t)r * N_CLASSES + c) = o;
}

// ---------------- launcher ----------------
extern "C" void kernel_launch(void* const* d_in, const int* in_sizes, int n_in,
                              void* d_out, int out_size) {
    (void)in_sizes; (void)n_in; (void)out_size;
    const float* x       = (const float*)d_in[0];
    const int*   task_id = (const int*)  d_in[1];
    const float* W1      = (const float*)d_in[2];
    const float* b1      = (const float*)d_in[3];
    const float* W2      = (const float*)d_in[4];
    const float* b2      = (const float*)d_in[5];
    float*       out     = (float*)d_out;

    static __nv_bfloat16 *p_xh = nullptr, *p_xl, *p_w1h, *p_w1l, *p_w2h, *p_w2l, *p_hh, *p_hl;
    static bool attr_done = false;
    if (!p_xh) {
        cudaGetSymbolAddress((void**)&p_xh,  g_xh);
        cudaGetSymbolAddress((void**)&p_xl,  g_xl);
        cudaGetSymbolAddress((void**)&p_w1h, g_w1h);
        cudaGetSymbolAddress((void**)&p_w1l, g_w1l);
        cudaGetSymbolAddress((void**)&p_w2h, g_w2h);
        cudaGetSymbolAddress((void**)&p_w2l, g_w2l);
        cudaGetSymbolAddress((void**)&p_hh,  g_hh);
        cudaGetSymbolAddress((void**)&p_hl,  g_hl);
    }
    if (!attr_done) {
        cudaFuncSetAttribute(gemm_kernel<0>, cudaFuncAttributeMaxDynamicSharedMemorySize, DYN_SMEM);
        cudaFuncSetAttribute(gemm_kernel<1>, cudaFuncAttributeMaxDynamicSharedMemorySize, DYN_SMEM);
        attr_done = true;
    }

    zero_counts_kernel<<<1, 32>>>();
    bucket_rows_kernel<<<(BATCH + 255) / 256, 256>>>(task_id);

    const int n8x = BATCH * D_MODEL / 8;
    split_kernel<<<(n8x + 255) / 256, 256>>>(x, p_xh, p_xl, n8x);
    const int n8w = N_TASKS * D_MODEL * HIDDEN / 8;
    split_kernel<<<(n8w + 255) / 256, 256>>>(W1, p_w1h, p_w1l, n8w);
    split_w2_kernel<<<(N_TASKS * KDIM * 32 + 255) / 256, 256>>>(W2, p_w2h, p_w2l);

    // layer 1: h = relu(x @ W1[t] + b1[t]) -> bf16 hi/lo
    dim3 g1(HIDDEN / BN, BATCH / BM, N_TASKS);
    gemm_kernel<0><<<g1, 256, DYN_SMEM>>>(p_xh, p_xl, p_w1h, p_w1l, b1,
                                          p_hh, p_hl, D_MODEL, HIDDEN, D_MODEL * HIDDEN);

    // layer 2: split-K=4 partials
    dim3 g2(4, BATCH / BM, N_TASKS);
    gemm_kernel<1><<<g2, 256, DYN_SMEM>>>(p_hh, p_hl, p_w2h, p_w2l, nullptr,
                                          nullptr, nullptr, KDIM, 128, KDIM * 128);

    // reduce + bias -> out
    reduce_kernel<<<(BATCH * 25 + 255) / 256, 256>>>(task_id, b2, out);
}

// round 9
// speedup vs baseline: 1.0854x; 1.0071x over previous
#include <cuda_runtime.h>
#include <cuda_bf16.h>
#include <cstdint>

#define N_TASKS   8
#define D_MODEL   1024
#define HIDDEN    1024
#define N_CLASSES 100
#define BATCH     8192
#define KDIM      1024

#define BM 128
#define BN 128
#define BK 32
#define ASTR 40                       // A smem row stride (bf16), 80B — ldmatrix conflict-free
#define BSTR 136                      // B smem row stride (bf16), 272B — ldmatrix.trans conflict-free
#define A_ELEMS (BM * ASTR)           // 5120
#define B_ELEMS (BK * BSTR)           // 4352
#define STAGE_ELEMS (2 * A_ELEMS + 2 * B_ELEMS)   // 18944
#define STAGE_B (STAGE_ELEMS * 2)                 // 37888 bytes
#define DYN_SMEM (2 * STAGE_B)                    // 75776 bytes -> 2 CTAs/SM guaranteed

// ---------------- device scratch (no allocations allowed) ----------------
__device__ int            g_counts[N_TASKS];
__device__ int            g_rowids[N_TASKS * BATCH];
__device__ __nv_bfloat16  g_xh[BATCH * D_MODEL];
__device__ __nv_bfloat16  g_xl[BATCH * D_MODEL];
__device__ __nv_bfloat16  g_w1h[N_TASKS * D_MODEL * HIDDEN];   // [t][k][n] natural
__device__ __nv_bfloat16  g_w1l[N_TASKS * D_MODEL * HIDDEN];
__device__ __nv_bfloat16  g_w2h[N_TASKS * KDIM * 128];         // [t][k][n pad 128]
__device__ __nv_bfloat16  g_w2l[N_TASKS * KDIM * 128];
__device__ __nv_bfloat16  g_hh[BATCH * HIDDEN];
__device__ __nv_bfloat16  g_hl[BATCH * HIDDEN];
__device__ float          g_part[4 * BATCH * 128];             // split-K=4 partials

// ---------------- PTX helpers ----------------
__device__ __forceinline__ uint32_t s2u(const void* p) {
    return (uint32_t)__cvta_generic_to_shared(p);
}
__device__ __forceinline__ void cp16(uint32_t dst, const void* src, bool v) {
    int sz = v ? 16 : 0;
    asm volatile("cp.async.cg.shared.global [%0], [%1], 16, %2;\n"
                 :: "r"(dst), "l"(src), "r"(sz));
}
#define CP_COMMIT asm volatile("cp.async.commit_group;\n" ::: "memory")
#define CP_WAIT0  asm volatile("cp.async.wait_group 0;\n" ::: "memory")

__device__ __forceinline__ void ldsm4(uint32_t* r, uint32_t addr) {
    asm volatile("ldmatrix.sync.aligned.m8n8.x4.shared.b16 {%0,%1,%2,%3}, [%4];"
                 : "=r"(r[0]), "=r"(r[1]), "=r"(r[2]), "=r"(r[3]) : "r"(addr));
}
__device__ __forceinline__ void ldsm4t(uint32_t* r, uint32_t addr) {
    asm volatile("ldmatrix.sync.aligned.m8n8.x4.trans.shared.b16 {%0,%1,%2,%3}, [%4];"
                 : "=r"(r[0]), "=r"(r[1]), "=r"(r[2]), "=r"(r[3]) : "r"(addr));
}
__device__ __forceinline__ void mma_bf16(float* c, const uint32_t* a, const uint32_t* b) {
    asm volatile(
        "mma.sync.aligned.m16n8k16.row.col.f32.bf16.bf16.f32 "
        "{%0,%1,%2,%3}, {%4,%5,%6,%7}, {%8,%9}, {%0,%1,%2,%3};\n"
        : "+f"(c[0]), "+f"(c[1]), "+f"(c[2]), "+f"(c[3])
        : "r"(a[0]), "r"(a[1]), "r"(a[2]), "r"(a[3]), "r"(b[0]), "r"(b[1]));
}

// ---------------- bucketing ----------------
__global__ void zero_counts_kernel() {
    if (threadIdx.x < N_TASKS) g_counts[threadIdx.x] = 0;
}
__global__ void bucket_rows_kernel(const int* __restrict__ task_id) {
    int b = blockIdx.x * blockDim.x + threadIdx.x;
    if (b < BATCH) {
        int t = task_id[b];
        int pos = atomicAdd(&g_counts[t], 1);
        g_rowids[t * BATCH + pos] = b;
    }
}

// ---------------- fp32 -> bf16 hi/lo splits ----------------
__global__ void split_kernel(const float* __restrict__ src,
                             __nv_bfloat16* __restrict__ dh,
                             __nv_bfloat16* __restrict__ dl, int n8) {
    int i = blockIdx.x * blockDim.x + threadIdx.x;
    if (i >= n8) return;
    float4 v0 = ((const float4*)src)[2 * i];
    float4 v1 = ((const float4*)src)[2 * i + 1];
    float v[8] = {v0.x, v0.y, v0.z, v0.w, v1.x, v1.y, v1.z, v1.w};
    alignas(16) __nv_bfloat16 h[8];
    alignas(16) __nv_bfloat16 l[8];
    #pragma unroll
    for (int k = 0; k < 8; k++) {
        __nv_bfloat16 hb = __float2bfloat16(v[k]);
        h[k] = hb;
        l[k] = __float2bfloat16(v[k] - __bfloat162float(hb));
    }
    ((uint4*)dh)[i] = *(uint4*)h;
    ((uint4*)dl)[i] = *(uint4*)l;
}

// W2 [T*K][100] -> padded [T*K][128] hi/lo bf16 (zero pad)
__global__ void split_w2_kernel(const float* __restrict__ W2,
                                __nv_bfloat16* __restrict__ dh,
                                __nv_bfloat16* __restrict__ dl) {
    int i = blockIdx.x * blockDim.x + threadIdx.x;      // (T*K) * 32
    if (i >= N_TASKS * KDIM * 32) return;
    int row = i >> 5, q = i & 31, c = q * 4;
    float v[4] = {0.f, 0.f, 0.f, 0.f};
    if (c < N_CLASSES) {
        float4 tv = *(const float4*)(W2 + (size_t)row * N_CLASSES + c);
        v[0] = tv.x; v[1] = tv.y; v[2] = tv.z; v[3] = tv.w;
    }
    alignas(8) __nv_bfloat16 h[4];
    alignas(8) __nv_bfloat16 l[4];
    #pragma unroll
    for (int k = 0; k < 4; k++) {
        __nv_bfloat16 hb = __float2bfloat16(v[k]);
        h[k] = hb;
        l[k] = __float2bfloat16(v[k] - __bfloat162float(hb));
    }
    ((uint2*)(dh + (size_t)row * 128))[q] = *(uint2*)h;
    ((uint2*)(dl + (size_t)row * 128))[q] = *(uint2*)l;
}

// ---------------- grouped GEMM, 3-term bf16 split, HMMA ----------------
// MODE 0: layer1 — blockIdx.x = n-tile; bias+relu; bf16 hi/lo out (ld=HIDDEN)
// MODE 1: layer2 — blockIdx.x = k-chunk (of 4); fp32 partials to g_part
template<int MODE>
__global__ __launch_bounds__(256, 2)
void gemm_kernel(const __nv_bfloat16* __restrict__ Ah,
                 const __nv_bfloat16* __restrict__ Al,
                 const __nv_bfloat16* __restrict__ Bh_,
                 const __nv_bfloat16* __restrict__ Bl_,
                 const float* __restrict__ bias,
                 __nv_bfloat16* __restrict__ Dh,
                 __nv_bfloat16* __restrict__ Dl,
                 int K, int ldB, int strideB_task) {
    const int t   = blockIdx.z;
    const int cnt = g_counts[t];
    const int m0  = blockIdx.y * BM;
    if (m0 >= cnt) return;

    int n0, kb0, KB;
    if (MODE == 0) { n0 = blockIdx.x * BN; kb0 = 0;                          KB = K / BK; }
    else           { n0 = 0;               kb0 = blockIdx.x * (K / (4 * BK)); KB = K / (4 * BK); }

    const __nv_bfloat16* Bh = Bh_ + (size_t)t * strideB_task;
    const __nv_bfloat16* Bl = Bl_ + (size_t)t * strideB_task;

    extern __shared__ __nv_bfloat16 sm[];
    __shared__ int rowid_s[BM];

    const int tid = threadIdx.x;
    if (tid < BM) {
        int m = m0 + tid;
        rowid_s[tid] = (m < cnt) ? g_rowids[t * BATCH + m] : -1;
    }
    __syncthreads();

    // ---- loader state ----
    // A: 512 16B-chunks per array (128 rows x 4 chunks of 8 bf16); units tid, tid+256
    const int arow0 = tid >> 2,         ac0 = tid & 3;
    const int arow1 = (tid + 256) >> 2, ac1 = (tid + 256) & 3;
    const int rA0 = rowid_s[arow0], rA1 = rowid_s[arow1];
    const bool av0 = (rA0 >= 0), av1 = (rA1 >= 0);
    const char* aH0 = (const char*)(Ah + (size_t)(av0 ? rA0 : 0) * K + kb0 * BK) + ac0 * 16;
    const char* aH1 = (const char*)(Ah + (size_t)(av1 ? rA1 : 0) * K + kb0 * BK) + ac1 * 16;
    const char* aL0 = (const char*)(Al + (size_t)(av0 ? rA0 : 0) * K + kb0 * BK) + ac0 * 16;
    const char* aL1 = (const char*)(Al + (size_t)(av1 ? rA1 : 0) * K + kb0 * BK) + ac1 * 16;
    const uint32_t aoff0 = (uint32_t)(arow0 * ASTR + ac0 * 8) * 2;
    const uint32_t aoff1 = (uint32_t)(arow1 * ASTR + ac1 * 8) * 2;

    // B: 512 16B-chunks per array (32 k-rows x 16 chunks of 8 bf16); units tid, tid+256
    const int bk0 = tid >> 4,         bc0 = tid & 15;
    const int bk1 = (tid + 256) >> 4, bc1 = (tid + 256) & 15;
    const char* bH0 = (const char*)(Bh + (size_t)(kb0 * BK + bk0) * ldB + n0 + bc0 * 8);
    const char* bH1 = (const char*)(Bh + (size_t)(kb0 * BK + bk1) * ldB + n0 + bc1 * 8);
    const char* bL0 = (const char*)(Bl + (size_t)(kb0 * BK + bk0) * ldB + n0 + bc0 * 8);
    const char* bL1 = (const char*)(Bl + (size_t)(kb0 * BK + bk1) * ldB + n0 + bc1 * 8);
    const uint32_t boff0 = (uint32_t)(bk0 * BSTR + bc0 * 8) * 2;
    const uint32_t boff1 = (uint32_t)(bk1 * BSTR + bc1 * 8) * 2;
    const size_t bstep = (size_t)BK * ldB * 2;   // bytes per k-block

    const uint32_t smu = s2u(sm);

    auto issue = [&](int stage, int kb) {
        uint32_t base = smu + stage * STAGE_B;
        size_t akb = (size_t)kb * (BK * 2);      // 64 B per row per k-block
        size_t bkb = (size_t)kb * bstep;
        cp16(base + aoff0, aH0 + akb, av0);
        cp16(base + aoff1, aH1 + akb, av1);
        cp16(base + 2 * A_ELEMS + aoff0, aL0 + akb, av0);
        cp16(base + 2 * A_ELEMS + aoff1, aL1 + akb, av1);
        cp16(base + 4 * A_ELEMS + boff0, bH0 + bkb, true);
        cp16(base + 4 * A_ELEMS + boff1, bH1 + bkb, true);
        cp16(base + 4 * A_ELEMS + 2 * B_ELEMS + boff0, bL0 + bkb, true);
        cp16(base + 4 * A_ELEMS + 2 * B_ELEMS + boff1, bL1 + bkb, true);
    };

    // ---- compute lane mapping ----
    const int warp = tid >> 5, lane = tid & 31;
    const int wm = warp >> 2;           // 0..1 (m half)
    const int wn = warp & 3;            // 0..3 (n quarter)
    const int g  = lane >> 2, tg = lane & 3;
    // A ldmatrix.x4: lanes 0-7 rows, 8-15 rows+8, 16-31 k+8
    const uint32_t a_lane = (uint32_t)(((wm * 64 + (lane & 7) + ((lane >> 3) & 1) * 8) * ASTR
                                        + ((lane >> 4) & 1) * 8) * 2);
    // B ldmatrix.x4.trans: lanes 0-7 k-rows, 8-15 k+8, 16-31 n+8
    const uint32_t b_lane = (uint32_t)((((lane & 7) + ((lane >> 3) & 1) * 8) * BSTR
                                        + ((lane >> 4) & 1) * 8 + wn * 32) * 2);

    float acc[4][4][4];
    #pragma unroll
    for (int i = 0; i < 4; i++)
        #pragma unroll
        for (int j = 0; j < 4; j++)
            #pragma unroll
            for (int q = 0; q < 4; q++) acc[i][j][q] = 0.f;

    auto compute = [&](int stage) {
        uint32_t base = smu + stage * STAGE_B;
        uint32_t uAh = base;
        uint32_t uAl = base + 2 * A_ELEMS;
        uint32_t uBh = base + 4 * A_ELEMS;
        uint32_t uBl = base + 4 * A_ELEMS + 2 * B_ELEMS;
        #pragma unroll
        for (int kk = 0; kk < BK; kk += 16) {
            uint32_t bh[2][4], bl[2][4];          // [jj] -> n-tiles 2jj, 2jj+1
            #pragma unroll
            for (int jj = 0; jj < 2; jj++) {
                uint32_t off = b_lane + (uint32_t)((kk * BSTR + jj * 16) * 2);
                ldsm4t(bh[jj], uBh + off);
                ldsm4t(bl[jj], uBl + off);
            }
            #pragma unroll
            for (int i = 0; i < 4; i++) {
                uint32_t ah[4], al[4];
                uint32_t off = a_lane + (uint32_t)((i * 16 * ASTR + kk) * 2);
                ldsm4(ah, uAh + off);
                ldsm4(al, uAl + off);
                // term-major: consecutive MMAs hit different accumulators
                #pragma unroll
                for (int j = 0; j < 4; j++)
                    mma_bf16(acc[i][j], ah, &bh[j >> 1][(j & 1) * 2]);
                #pragma unroll
                for (int j = 0; j < 4; j++)
                    mma_bf16(acc[i][j], ah, &bl[j >> 1][(j & 1) * 2]);
                #pragma unroll
                for (int j = 0; j < 4; j++)
                    mma_bf16(acc[i][j], al, &bh[j >> 1][(j & 1) * 2]);
            }
        }
    };

    // ---- 2-stage mainloop, SINGLE sync per iteration ----
    // Order: wait(data kb) -> sync -> issue(kb+1) -> compute(kb).
    // issue(kb+1) writes stage (kb+1)&1, whose last reader compute(kb-1)
    // finished before this iteration's sync (program order per warp).
    issue(0, 0); CP_COMMIT;
    for (int kb = 0; kb < KB; kb++) {
        CP_WAIT0;
        __syncthreads();
        if (kb + 1 < KB) { issue((kb + 1) & 1, kb + 1); CP_COMMIT; }
        compute(kb & 1);
    }

    // ---- epilogue ----
    if (MODE == 0) {
        const float* bT = bias + (size_t)t * HIDDEN;
        #pragma unroll
        for (int j = 0; j < 4; j++) {
            int c = n0 + wn * 32 + j * 8 + 2 * tg;
            float bc0 = bT[c], bc1 = bT[c + 1];
            #pragma unroll
            for (int i = 0; i < 4; i++) {
                int lr = wm * 64 + i * 16 + g;
                int r0 = rowid_s[lr], r1 = rowid_s[lr + 8];
                if (r0 >= 0) {
                    float v0 = acc[i][j][0] + bc0; v0 = v0 > 0.f ? v0 : 0.f;
                    float v1 = acc[i][j][1] + bc1; v1 = v1 > 0.f ? v1 : 0.f;
                    __nv_bfloat16 h0 = __float2bfloat16(v0), h1 = __float2bfloat16(v1);
                    __nv_bfloat16 l0 = __float2bfloat16(v0 - __bfloat162float(h0));
                    __nv_bfloat16 l1 = __float2bfloat16(v1 - __bfloat162float(h1));
                    *(__nv_bfloat162*)&Dh[(size_t)r0 * HIDDEN + c] = __nv_bfloat162(h0, h1);
                    *(__nv_bfloat162*)&Dl[(size_t)r0 * HIDDEN + c] = __nv_bfloat162(l0, l1);
                }
                if (r1 >= 0) {
                    float v0 = acc[i][j][2] + bc0; v0 = v0 > 0.f ? v0 : 0.f;
                    float v1 = acc[i][j][3] + bc1; v1 = v1 > 0.f ? v1 : 0.f;
                    __nv_bfloat16 h0 = __float2bfloat16(v0), h1 = __float2bfloat16(v1);
                    __nv_bfloat16 l0 = __float2bfloat16(v0 - __bfloat162float(h0));
                    __nv_bfloat16 l1 = __float2bfloat16(v1 - __bfloat162float(h1));
                    *(__nv_bfloat162*)&Dh[(size_t)r1 * HIDDEN + c] = __nv_bfloat162(h0, h1);
                    *(__nv_bfloat162*)&Dl[(size_t)r1 * HIDDEN + c] = __nv_bfloat162(l0, l1);
                }
            }
        }
    } else {
        float* P = g_part + (size_t)blockIdx.x * BATCH * 128;
        #pragma unroll
        for (int j = 0; j < 4; j++) {
            int c = wn * 32 + j * 8 + 2 * tg;
            #pragma unroll
            for (int i = 0; i < 4; i++) {
                int lr = wm * 64 + i * 16 + g;
                int r0 = rowid_s[lr], r1 = rowid_s[lr + 8];
                if (r0 >= 0)
                    *(float2*)(P + (size_t)r0 * 128 + c) = make_float2(acc[i][j][0], acc[i][j][1]);
                if (r1 >= 0)
                    *(float2*)(P + (size_t)r1 * 128 + c) = make_float2(acc[i][j][2], acc[i][j][3]);
            }
        }
    }
}

// ---------------- split-K reduce + bias for layer2 ----------------
__global__ void reduce_kernel(const int* __restrict__ task_id,
                              const float* __restrict__ b2,
                              float* __restrict__ out) {
    int i = blockIdx.x * blockDim.x + threadIdx.x;   // BATCH * 25
    if (i >= BATCH * 25) return;
    int r = i / 25, q = i % 25, c = q * 4;
    int t = task_id[r];
    float4 s0 = *(const float4*)(g_part + ((size_t)0 * BATCH + r) * 128 + c);
    float4 s1 = *(const float4*)(g_part + ((size_t)1 * BATCH + r) * 128 + c);
    float4 s2 = *(const float4*)(g_part + ((size_t)2 * BATCH + r) * 128 + c);
    float4 s3 = *(const float4*)(g_part + ((size_t)3 * BATCH + r) * 128 + c);
    float4 b  = *(const float4*)(b2 + (size_t)t * N_CLASSES + c);
    float4 o;
    o.x = s0.x + s1.x + s2.x + s3.x + b.x;
    o.y = s0.y + s1.y + s2.y + s3.y + b.y;
    o.z = s0.z + s1.z + s2.z + s3.z + b.z;
    o.w = s0.w + s1.w + s2.w + s3.w + b.w;
    *(float4*)(out + (size_t)r * N_CLASSES + c) = o;
}

// ---------------- launcher ----------------
extern "C" void kernel_launch(void* const* d_in, const int* in_sizes, int n_in,
                              void* d_out, int out_size) {
    (void)in_sizes; (void)n_in; (void)out_size;
    const float* x       = (const float*)d_in[0];
    const int*   task_id = (const int*)  d_in[1];
    const float* W1      = (const float*)d_in[2];
    const float* b1      = (const float*)d_in[3];
    const float* W2      = (const float*)d_in[4];
    const float* b2      = (const float*)d_in[5];
    float*       out     = (float*)d_out;

    static __nv_bfloat16 *p_xh = nullptr, *p_xl, *p_w1h, *p_w1l, *p_w2h, *p_w2l, *p_hh, *p_hl;
    static bool attr_done = false;
    if (!p_xh) {
        cudaGetSymbolAddress((void**)&p_xh,  g_xh);
        cudaGetSymbolAddress((void**)&p_xl,  g_xl);
        cudaGetSymbolAddress((void**)&p_w1h, g_w1h);
        cudaGetSymbolAddress((void**)&p_w1l, g_w1l);
        cudaGetSymbolAddress((void**)&p_w2h, g_w2h);
        cudaGetSymbolAddress((void**)&p_w2l, g_w2l);
        cudaGetSymbolAddress((void**)&p_hh,  g_hh);
        cudaGetSymbolAddress((void**)&p_hl,  g_hl);
    }
    if (!attr_done) {
        cudaFuncSetAttribute(gemm_kernel<0>, cudaFuncAttributeMaxDynamicSharedMemorySize, DYN_SMEM);
        cudaFuncSetAttribute(gemm_kernel<1>, cudaFuncAttributeMaxDynamicSharedMemorySize, DYN_SMEM);
        attr_done = true;
    }

    zero_counts_kernel<<<1, 32>>>();
    bucket_rows_kernel<<<(BATCH + 255) / 256, 256>>>(task_id);

    const int n8x = BATCH * D_MODEL / 8;
    split_kernel<<<(n8x + 255) / 256, 256>>>(x, p_xh, p_xl, n8x);
    const int n8w = N_TASKS * D_MODEL * HIDDEN / 8;
    split_kernel<<<(n8w + 255) / 256, 256>>>(W1, p_w1h, p_w1l, n8w);
    split_w2_kernel<<<(N_TASKS * KDIM * 32 + 255) / 256, 256>>>(W2, p_w2h, p_w2l);

    // layer 1: h = relu(x @ W1[t] + b1[t]) -> bf16 hi/lo
    dim3 g1(HIDDEN / BN, BATCH / BM, N_TASKS);
    gemm_kernel<0><<<g1, 256, DYN_SMEM>>>(p_xh, p_xl, p_w1h, p_w1l, b1,
                                          p_hh, p_hl, D_MODEL, HIDDEN, D_MODEL * HIDDEN);

    // layer 2: split-K=4 partials
    dim3 g2(4, BATCH / BM, N_TASKS);
    gemm_kernel<1><<<g2, 256, DYN_SMEM>>>(p_hh, p_hl, p_w2h, p_w2l, nullptr,
                                          nullptr, nullptr, KDIM, 128, KDIM * 128);

    // reduce + bias -> out
    reduce_kernel<<<(BATCH * 25 + 255) / 256, 256>>>(task_id, b2, out);
}